// round 9
// baseline (speedup 1.0000x reference)
#include <cuda_runtime.h>
#include <math.h>
#include <stdint.h>

#define NMAX 200064
#define GCX 512
#define GCY 48
#define GBX 220
#define GBY 250
#define BEV_SXY (GBX*GBY)
#define BEV_SY  GBY
#define IMG_ELEMS (4*64*GCX*GCY)

static __device__ __align__(16) float g_bev_acc[4*GBX*GBY*4];
static __device__ __align__(16) float g_cyl_acc[4*GCX*GCY*4];
static __device__ __align__(16) float g_h1[(size_t)NMAX*64];
static __device__ __align__(16) float g_h2[(size_t)NMAX*128];
static __device__ __align__(16) float g_h3[(size_t)NMAX*64];
static __device__ __align__(16) float g_img_in[IMG_ELEMS];   // [b][c][512][48]
static __device__ __align__(16) float g_gimg[IMG_ELEMS];     // [b][512][48][c]
static __device__ double g_stats[640];
static __device__ float g_sc1[64], g_sh1[64];
static __device__ float g_sc2[128], g_sh2[128];
static __device__ float g_sc3[64], g_sh3[64];
static __device__ float g_scC[64], g_shC[64];

__global__ void k_zeroall(float* bev, int n1, float* outmax, int n5){
    int i = blockIdx.x*blockDim.x + threadIdx.x;
    int stride = gridDim.x*blockDim.x;
    if (i < 4*GCX*GCY*4) g_cyl_acc[i] = 0.f;
    if (i < 640) g_stats[i] = 0.0;
    for (int j = i; j < n1; j += stride) bev[j] = 0.f;
    for (int j = i; j < n5; j += stride) outmax[j] = 0.f;
    for (int j = i; j < IMG_ELEMS; j += stride) g_img_in[j] = 0.f;
}

__global__ void __launch_bounds__(256) k_stats(const float* __restrict__ X, int n, int C, double* out){
    __shared__ float sb[256];
    int t = threadIdx.x;
    for (int i = t; i < 2*C; i += 256) sb[i] = 0.f;
    __syncthreads();
    int c4n = C >> 2;
    int c4  = t % c4n;
    int rl  = t / c4n;
    int rstep = 256 / c4n;
    int per = (n + gridDim.x - 1) / gridDim.x;
    int r0 = blockIdx.x * per;
    int rend = r0 + per; if (rend > n) rend = n;
    float4 s  = make_float4(0,0,0,0);
    float4 ss = make_float4(0,0,0,0);
    #pragma unroll 4
    for (int r = r0 + rl; r < rend; r += rstep){
        float4 v = *(const float4*)(X + (size_t)r*C + c4*4);
        s.x += v.x; s.y += v.y; s.z += v.z; s.w += v.w;
        ss.x += v.x*v.x; ss.y += v.y*v.y; ss.z += v.z*v.z; ss.w += v.w*v.w;
    }
    atomicAdd(&sb[c4*4+0], s.x);  atomicAdd(&sb[c4*4+1], s.y);
    atomicAdd(&sb[c4*4+2], s.z);  atomicAdd(&sb[c4*4+3], s.w);
    atomicAdd(&sb[C+c4*4+0], ss.x); atomicAdd(&sb[C+c4*4+1], ss.y);
    atomicAdd(&sb[C+c4*4+2], ss.z); atomicAdd(&sb[C+c4*4+3], ss.w);
    __syncthreads();
    for (int i = t; i < 2*C; i += 256)
        atomicAdd(&out[i], (double)sb[i]);
}

__global__ void k_fin(const double* st, const float* __restrict__ g,
                      const float* __restrict__ b, float* sc, float* sh, double cnt){
    int c = threadIdx.x, C = blockDim.x;
    double m = st[c] / cnt;
    double v = st[C + c] / cnt - m*m;
    double s = (double)g[c] / sqrt(v + 1e-3);
    sc[c] = (float)s;
    sh[c] = (float)((double)b[c] - m*s);
}

__global__ void k_segsum(const float* __restrict__ pts, const float* __restrict__ pcyl,
                         const int* __restrict__ binv, const int* __restrict__ cinv, int n){
    int p = blockIdx.x*blockDim.x + threadIdx.x;
    if (p >= n) return;
    int bi = binv[p], ci = cinv[p];
    atomicAdd(&g_bev_acc[bi*4+0], pts[p*5+1]);
    atomicAdd(&g_bev_acc[bi*4+1], pts[p*5+2]);
    atomicAdd(&g_bev_acc[bi*4+2], pts[p*5+3]);
    atomicAdd(&g_bev_acc[bi*4+3], 1.f);
    atomicAdd(&g_cyl_acc[ci*4+0], pcyl[p*3+0]);
    atomicAdd(&g_cyl_acc[ci*4+1], pcyl[p*3+1]);
    atomicAdd(&g_cyl_acc[ci*4+2], pcyl[p*3+2]);
    atomicAdd(&g_cyl_acc[ci*4+3], 1.f);
}

__global__ void k_mvf_gemm1(const float* __restrict__ pts, const float* __restrict__ pcyl,
                            const float* __restrict__ cylidx, const float* __restrict__ bevidx,
                            const int* __restrict__ binv, const int* __restrict__ cinv,
                            const float* __restrict__ w1, int n){
    __shared__ float w1s[1024];
    int t = threadIdx.x;
    for (int i = t; i < 1024; i += 256) w1s[i] = w1[i];
    __syncthreads();
    int p = blockIdx.x*256 + t;
    if (p >= n) return;

    float x = pts[p*5+1], y = pts[p*5+2], z = pts[p*5+3], inten = pts[p*5+4];
    float ph = pcyl[p*3+0], zc = pcyl[p*3+1], rh = pcyl[p*3+2];
    float bc0 = floorf(bevidx[p*2+0]), bc1 = floorf(bevidx[p*2+1]);
    float cc0 = floorf(cylidx[p*2+0]), cc1 = floorf(cylidx[p*2+1]);

    int bi = binv[p], ci = cinv[p];
    float4 ba = *(const float4*)&g_bev_acc[bi*4];
    float4 ca = *(const float4*)&g_cyl_acc[ci*4];

    const float CVS0 = (float)((3.14159265 + 3.14159265) / 512.0);
    float f[16];
    f[0]=x; f[1]=y; f[2]=z; f[3]=ph; f[4]=zc; f[5]=rh;
    f[6]=x - ((bc0+0.5f)*0.32f);
    f[7]=y - ((bc1+0.5f)*0.32f - 40.0f);
    f[8]=ph - ((cc0+0.5f)*CVS0 - 3.14159265f);
    f[9]=zc - ((cc1+0.5f)*0.125f - 2.0f);
    f[10]=x - ba.x/ba.w; f[11]=y - ba.y/ba.w;
    f[12]=ph - ca.x/ca.w; f[13]=zc - ca.y/ca.w;
    f[14]=sqrtf(x*x + y*y + z*z);
    f[15]=inten;

    float* outp = g_h1 + (size_t)p*64;
    #pragma unroll
    for (int og = 0; og < 16; og++){
        const float* wr = w1s + og*64;
        float o0=0.f,o1=0.f,o2=0.f,o3=0.f;
        #pragma unroll
        for (int k = 0; k < 16; k++){
            float fk = f[k];
            o0 += fk*wr[k];    o1 += fk*wr[16+k];
            o2 += fk*wr[32+k]; o3 += fk*wr[48+k];
        }
        *(float4*)(outp + og*4) = make_float4(o0,o1,o2,o3);
    }
}

// h2[Nx128] = bnrelu(h1)[Nx64] @ w2^T  (R4-proven: 64-pt blocks, 8x4 per thread)
__global__ void __launch_bounds__(256) k_gemm2(const float* __restrict__ w2, int n){
    extern __shared__ float sm[];
    float* As = sm;            // [64][65]
    float* Bs = sm + 64*65;    // [64][132]
    int t = threadIdx.x;
    int p0 = blockIdx.x * 64;

    for (int idx = t; idx < 8192; idx += 256){
        int o = idx >> 6, k = idx & 63;
        Bs[k*132 + o] = w2[idx];
    }
    for (int idx = t; idx < 4096; idx += 256){
        int pl = idx >> 6, k = idx & 63;
        int p = p0 + pl;
        float v = 0.f;
        if (p < n){
            v = g_h1[(size_t)p*64 + k];
            v = fmaxf(g_sc1[k]*v + g_sh1[k], 0.f);
        }
        As[k*65 + pl] = v;
    }
    __syncthreads();

    int o0 = (t & 31) * 4;
    int pq = (t >> 5) * 8;
    float acc[8][4];
    #pragma unroll
    for (int i=0;i<8;i++){ acc[i][0]=0;acc[i][1]=0;acc[i][2]=0;acc[i][3]=0; }

    for (int k = 0; k < 64; k++){
        float4 bv = *(const float4*)(Bs + k*132 + o0);
        #pragma unroll
        for (int i = 0; i < 8; i++){
            float a = As[k*65 + pq + i];
            acc[i][0] += a*bv.x; acc[i][1] += a*bv.y;
            acc[i][2] += a*bv.z; acc[i][3] += a*bv.w;
        }
    }
    #pragma unroll
    for (int i = 0; i < 8; i++){
        int p = p0 + pq + i;
        if (p < n)
            *(float4*)(g_h2 + (size_t)p*128 + o0) =
                make_float4(acc[i][0],acc[i][1],acc[i][2],acc[i][3]);
    }
}

__global__ void k_scatmax(const float* __restrict__ pts, const float* __restrict__ cylidx, int n){
    int p = blockIdx.x*256 + threadIdx.x;
    if (p >= n) return;
    int b  = (int)pts[p*5];
    int cx = (int)floorf(cylidx[p*2+0]);
    int cy = (int)floorf(cylidx[p*2+1]);
    size_t base0 = ((size_t)(b*64)*GCX + cx)*GCY + cy;
    const float4* hp = (const float4*)(g_h2 + (size_t)p*128);
    #pragma unroll
    for (int q = 0; q < 16; q++){
        float4 h = hp[q];
        float hv[4] = {h.x,h.y,h.z,h.w};
        #pragma unroll
        for (int j = 0; j < 4; j++){
            int c = q*4 + j;
            float v = fmaxf(g_sc2[c]*hv[j] + g_sh2[c], 0.f);
            atomicMax((unsigned int*)&g_img_in[base0 + (size_t)c*(GCX*GCY)], __float_as_uint(v));
        }
    }
}

// conv 3x3 SAME, 64->64, [b][c][512][48] -> channel-last [b][512][48][64]  (R4 proven)
__global__ void __launch_bounds__(384,2) k_conv(const float* __restrict__ wcp){
    extern __shared__ float sm[];
    float* in_s = sm;          // [16][6][50]
    float* w_s  = sm + 4800;   // [16*9][64]
    int t = threadIdx.x;
    int ocg = t & 7;
    int yg  = (t >> 3) % 12;
    int xl  = t / 96;
    int b = blockIdx.y;
    int x0 = blockIdx.x * 4;
    int oc0 = ocg*8, y0 = yg*4;

    float acc[8][4];
    #pragma unroll
    for (int o=0;o<8;o++){ acc[o][0]=0;acc[o][1]=0;acc[o][2]=0;acc[o][3]=0; }

    for (int icc = 0; icc < 4; icc++){
        __syncthreads();
        for (int idx = t; idx < 4800; idx += 384){
            int ic = idx / 300, r = idx % 300;
            int sx = r / 50, yy = r % 50;
            int gx = x0 - 1 + sx, gy = yy - 1;
            float v = 0.f;
            if (gx >= 0 && gx < GCX && gy >= 0 && gy < GCY)
                v = g_img_in[((size_t)(b*64 + icc*16 + ic)*GCX + gx)*GCY + gy];
            in_s[idx] = v;
        }
        for (int idx = t; idx < 9216; idx += 384){
            int oc = idx / 144, r = idx % 144;
            int ic = r / 9, tap = r % 9;
            w_s[(ic*9 + tap)*64 + oc] = wcp[((size_t)oc*64 + icc*16 + ic)*9 + tap];
        }
        __syncthreads();

        #pragma unroll 2
        for (int ic = 0; ic < 16; ic++){
            #pragma unroll
            for (int dx = 0; dx < 3; dx++){
                float iv[6];
                int base = (ic*6 + xl + dx)*50 + y0;
                #pragma unroll
                for (int j = 0; j < 6; j++) iv[j] = in_s[base + j];
                #pragma unroll
                for (int dy = 0; dy < 3; dy++){
                    const float* wr = w_s + (ic*9 + dx*3 + dy)*64 + oc0;
                    float4 wA = *(const float4*)wr;
                    float4 wB = *(const float4*)(wr + 4);
                    #pragma unroll
                    for (int i = 0; i < 4; i++){
                        float v = iv[dy + i];
                        acc[0][i] += wA.x*v; acc[1][i] += wA.y*v;
                        acc[2][i] += wA.z*v; acc[3][i] += wA.w*v;
                        acc[4][i] += wB.x*v; acc[5][i] += wB.y*v;
                        acc[6][i] += wB.z*v; acc[7][i] += wB.w*v;
                    }
                }
            }
        }
    }
    int X = x0 + xl;
    #pragma unroll
    for (int i = 0; i < 4; i++){
        size_t addr = ((size_t)(b*GCX + X)*GCY + (y0 + i))*64 + oc0;
        *(float4*)(g_gimg + addr)     = make_float4(acc[0][i],acc[1][i],acc[2][i],acc[3][i]);
        *(float4*)(g_gimg + addr + 4) = make_float4(acc[4][i],acc[5][i],acc[6][i],acc[7][i]);
    }
}

// h3[Nx64] = [bnrelu(h2[:,64:]) , bilerp(bnrelu_conv(gimg))] @ w3^T  (R4-proven: 64-pt blocks)
__global__ void __launch_bounds__(256) k_gemm3(const float* __restrict__ pts,
                                               const float* __restrict__ cylidx,
                                               const float* __restrict__ w3, int n){
    extern __shared__ float sm[];
    float* As = sm;            // [128][65]
    float* Bs = sm + 128*65;   // [128][68]
    int t = threadIdx.x;
    int p0 = blockIdx.x * 64;

    for (int idx = t; idx < 8192; idx += 256){
        int o = idx >> 7, k = idx & 127;
        Bs[k*68 + o] = w3[idx];
    }
    for (int idx = t; idx < 4096; idx += 256){
        int pl = idx >> 6, j = idx & 63;
        int p = p0 + pl;
        float v = 0.f;
        if (p < n){
            v = g_h2[(size_t)p*128 + 64 + j];
            v = fmaxf(g_sc2[64+j]*v + g_sh2[64+j], 0.f);
        }
        As[j*65 + pl] = v;
    }
    {
        int pl = t >> 2, seg = t & 3;
        int p = p0 + pl;
        int c0 = seg*16;
        if (p < n){
            float yq = cylidx[p*2+0], xq = cylidx[p*2+1];
            int y0i = (int)floorf(yq), y1i = y0i + 1;
            y0i = min(max(y0i,0), GCX-1); y1i = min(max(y1i,0), GCX-1);
            int x0i = (int)floorf(xq), x1i = x0i + 1;
            x0i = min(max(x0i,0), GCY-1); x1i = min(max(x1i,0), GCY-1);
            float x0f=(float)x0i, x1f=(float)x1i, y0f=(float)y0i, y1f=(float)y1i;
            float wa  = (x1f-xq)*(y1f-yq);
            float wb2 = (x1f-xq)*(yq-y0f);
            float wc2 = (xq-x0f)*(y1f-yq);
            float wd  = (xq-x0f)*(yq-y0f);
            int b = (int)pts[p*5];
            size_t ba_ = ((size_t)(b*GCX + y0i)*GCY + x0i)*64;
            size_t bb_ = ((size_t)(b*GCX + y1i)*GCY + x0i)*64;
            size_t bc_ = ((size_t)(b*GCX + y0i)*GCY + x1i)*64;
            size_t bd_ = ((size_t)(b*GCX + y1i)*GCY + x1i)*64;
            #pragma unroll
            for (int q = 0; q < 4; q++){
                int c = c0 + q*4;
                float4 A4 = *(const float4*)(g_gimg + ba_ + c);
                float4 B4 = *(const float4*)(g_gimg + bb_ + c);
                float4 C4 = *(const float4*)(g_gimg + bc_ + c);
                float4 D4 = *(const float4*)(g_gimg + bd_ + c);
                float Af[4]={A4.x,A4.y,A4.z,A4.w};
                float Bf[4]={B4.x,B4.y,B4.z,B4.w};
                float Cf[4]={C4.x,C4.y,C4.z,C4.w};
                float Df[4]={D4.x,D4.y,D4.z,D4.w};
                #pragma unroll
                for (int j = 0; j < 4; j++){
                    int cc2 = c + j;
                    float s = g_scC[cc2], h = g_shC[cc2];
                    float va = fmaxf(s*Af[j] + h, 0.f);
                    float vb = fmaxf(s*Bf[j] + h, 0.f);
                    float vc = fmaxf(s*Cf[j] + h, 0.f);
                    float vd = fmaxf(s*Df[j] + h, 0.f);
                    As[(64 + cc2)*65 + pl] = wa*va + wb2*vb + wc2*vc + wd*vd;
                }
            }
        } else {
            #pragma unroll
            for (int q = 0; q < 16; q++) As[(64 + c0 + q)*65 + pl] = 0.f;
        }
    }
    __syncthreads();

    int o0 = (t & 15) * 4;
    int pq = (t >> 4) * 4;
    float acc[4][4];
    #pragma unroll
    for (int i=0;i<4;i++){ acc[i][0]=0;acc[i][1]=0;acc[i][2]=0;acc[i][3]=0; }

    for (int k = 0; k < 128; k++){
        float4 bv = *(const float4*)(Bs + k*68 + o0);
        #pragma unroll
        for (int i = 0; i < 4; i++){
            float a = As[k*65 + pq + i];
            acc[i][0] += a*bv.x; acc[i][1] += a*bv.y;
            acc[i][2] += a*bv.z; acc[i][3] += a*bv.w;
        }
    }
    #pragma unroll
    for (int i = 0; i < 4; i++){
        int p = p0 + pq + i;
        if (p < n)
            *(float4*)(g_h3 + (size_t)p*64 + o0) =
                make_float4(acc[i][0],acc[i][1],acc[i][2],acc[i][3]);
    }
}

__global__ void k_out(const int* __restrict__ binv, float* __restrict__ out, int n){
    int p = blockIdx.x*256 + threadIdx.x;
    if (p >= n) return;
    int bi = binv[p];
    float* op = out + (size_t)p*64;
    float* mp = out + (size_t)n*64 + (size_t)bi*64;
    const float4* hp = (const float4*)(g_h3 + (size_t)p*64);
    #pragma unroll
    for (int q = 0; q < 16; q++){
        float4 h = hp[q];
        float hv[4] = {h.x,h.y,h.z,h.w};
        float rv[4];
        #pragma unroll
        for (int j = 0; j < 4; j++){
            int c = q*4 + j;
            rv[j] = fmaxf(g_sc3[c]*hv[j] + g_sh3[c], 0.f);
            atomicMax((unsigned int*)&mp[c], __float_as_uint(rv[j]));
        }
        *(float4*)(op + q*4) = make_float4(rv[0],rv[1],rv[2],rv[3]);
    }
}

__global__ void k_voxel(const int* __restrict__ coords, float* __restrict__ out, int n, int nb){
    int i = blockIdx.x*blockDim.x + threadIdx.x;
    if (i >= nb) return;
    int c = coords[i];
    int vb = c / BEV_SXY;
    int rem = c % BEV_SXY;
    float* o = out + (size_t)n*64 + (size_t)nb*64 + (size_t)i*4;
    o[0] = (float)vb; o[1] = 0.f;
    o[2] = (float)(rem % BEV_SY); o[3] = (float)(rem / BEV_SY);
}

static inline int cdiv(int a, int b){ return (a + b - 1) / b; }

extern "C" void kernel_launch(void* const* d_in, const int* in_sizes, int n_in,
                              void* d_out, int out_size){
    const float* pts    = (const float*)d_in[0];
    const float* pcyl   = (const float*)d_in[1];
    const float* cylidx = (const float*)d_in[2];
    const float* bevidx = (const float*)d_in[3];
    const float* w1 = (const float*)d_in[4];
    const float* g1 = (const float*)d_in[5];
    const float* b1 = (const float*)d_in[6];
    const float* w2 = (const float*)d_in[7];
    const float* g2 = (const float*)d_in[8];
    const float* b2 = (const float*)d_in[9];
    const float* wcp = (const float*)d_in[10];
    const float* gc = (const float*)d_in[11];
    const float* bc = (const float*)d_in[12];
    const float* w3 = (const float*)d_in[13];
    const float* g3 = (const float*)d_in[14];
    const float* b3 = (const float*)d_in[15];
    const int* binv    = (const int*)d_in[16];
    const int* bcoords = (const int*)d_in[17];
    const int* cinv    = (const int*)d_in[18];
    (void)n_in; (void)out_size;

    int N  = in_sizes[16];
    int Nb = in_sizes[17];
    float* out = (float*)d_out;

    float *p_bev,*p_gimg,*p_h1,*p_h2,*p_h3;
    float *p_sc1,*p_sh1,*p_sc2,*p_sh2,*p_sc3,*p_sh3,*p_scC,*p_shC;
    double* p_st;
    cudaGetSymbolAddress((void**)&p_bev,  g_bev_acc);
    cudaGetSymbolAddress((void**)&p_gimg, g_gimg);
    cudaGetSymbolAddress((void**)&p_h1,   g_h1);
    cudaGetSymbolAddress((void**)&p_h2,   g_h2);
    cudaGetSymbolAddress((void**)&p_h3,   g_h3);
    cudaGetSymbolAddress((void**)&p_st,   g_stats);
    cudaGetSymbolAddress((void**)&p_sc1,  g_sc1);
    cudaGetSymbolAddress((void**)&p_sh1,  g_sh1);
    cudaGetSymbolAddress((void**)&p_sc2,  g_sc2);
    cudaGetSymbolAddress((void**)&p_sh2,  g_sh2);
    cudaGetSymbolAddress((void**)&p_sc3,  g_sc3);
    cudaGetSymbolAddress((void**)&p_sh3,  g_sh3);
    cudaGetSymbolAddress((void**)&p_scC,  g_scC);
    cudaGetSymbolAddress((void**)&p_shC,  g_shC);

    k_zeroall<<<27024,256>>>(p_bev, Nb*4, out + (size_t)N*64, Nb*64);

    k_segsum<<<cdiv(N,256),256>>>(pts, pcyl, binv, cinv, N);
    k_mvf_gemm1<<<cdiv(N,256),256>>>(pts, pcyl, cylidx, bevidx, binv, cinv, w1, N);
    k_stats<<<1480,256>>>(p_h1, N, 64, p_st + 0);
    k_fin<<<1,64>>>(p_st + 0, g1, b1, p_sc1, p_sh1, (double)N);

    cudaFuncSetAttribute(k_gemm2, cudaFuncAttributeMaxDynamicSharedMemorySize, 50432);
    k_gemm2<<<cdiv(N,64),256,50432>>>(w2, N);
    k_stats<<<1480,256>>>(p_h2, N, 128, p_st + 128);
    k_fin<<<1,128>>>(p_st + 128, g2, b2, p_sc2, p_sh2, (double)N);

    k_scatmax<<<cdiv(N,256),256>>>(pts, cylidx, N);

    cudaFuncSetAttribute(k_conv, cudaFuncAttributeMaxDynamicSharedMemorySize, 56064);
    k_conv<<<dim3(128,4),384,56064>>>(wcp);
    k_stats<<<1480,256>>>(p_gimg, 4*GCX*GCY, 64, p_st + 512);
    k_fin<<<1,64>>>(p_st + 512, gc, bc, p_scC, p_shC, (double)(4*GCX*GCY));

    cudaFuncSetAttribute(k_gemm3, cudaFuncAttributeMaxDynamicSharedMemorySize, 68096);
    k_gemm3<<<cdiv(N,64),256,68096>>>(pts, cylidx, w3, N);
    k_stats<<<1480,256>>>(p_h3, N, 64, p_st + 384);
    k_fin<<<1,64>>>(p_st + 384, g3, b3, p_sc3, p_sh3, (double)N);

    k_out<<<cdiv(N,256),256>>>(binv, out, N);
    k_voxel<<<cdiv(Nb,256),256>>>(bcoords, out, N, Nb);
}

// round 10
// speedup vs baseline: 1.0468x; 1.0468x over previous
#include <cuda_runtime.h>
#include <math.h>
#include <stdint.h>

#define NMAX 200064
#define GCX 512
#define GCY 48
#define GBX 220
#define GBY 250
#define BEV_SXY (GBX*GBY)
#define BEV_SY  GBY
#define IMG_ELEMS (4*64*GCX*GCY)

static __device__ __align__(16) float g_bev_acc[4*GBX*GBY*4];
static __device__ __align__(16) float g_cyl_acc[4*GCX*GCY*4];
static __device__ __align__(16) float g_h1[(size_t)NMAX*64];
static __device__ __align__(16) float g_h2[(size_t)NMAX*128];
static __device__ __align__(16) float g_h3[(size_t)NMAX*64];
static __device__ __align__(16) float g_img_in[IMG_ELEMS];   // [b][c][512][48]
static __device__ __align__(16) float g_gimg[IMG_ELEMS];     // [b][512][48][c]
static __device__ double g_stats[640];
static __device__ float g_sc1[64], g_sh1[64];
static __device__ float g_sc2[128], g_sh2[128];
static __device__ float g_sc3[64], g_sh3[64];
static __device__ float g_scC[64], g_shC[64];

__global__ void k_zeroall(float* bev, int n1, float* outmax, int n5){
    int i = blockIdx.x*blockDim.x + threadIdx.x;
    int stride = gridDim.x*blockDim.x;
    if (i < 4*GCX*GCY*4) g_cyl_acc[i] = 0.f;
    if (i < 640) g_stats[i] = 0.0;
    for (int j = i; j < n1; j += stride) bev[j] = 0.f;
    for (int j = i; j < n5; j += stride) outmax[j] = 0.f;
    for (int j = i; j < IMG_ELEMS; j += stride) g_img_in[j] = 0.f;
}

// R4-proven stats: fp32 partials, shared combine, 1 double atomic per col per block
__global__ void __launch_bounds__(256) k_stats(const float* __restrict__ X, int n, int C, double* out){
    __shared__ float sb[256];
    int t = threadIdx.x;
    for (int i = t; i < 2*C; i += 256) sb[i] = 0.f;
    __syncthreads();
    int c4n = C >> 2;
    int c4  = t % c4n;
    int rl  = t / c4n;
    int rstep = 256 / c4n;
    int per = (n + gridDim.x - 1) / gridDim.x;
    int r0 = blockIdx.x * per;
    int rend = r0 + per; if (rend > n) rend = n;
    float4 s  = make_float4(0,0,0,0);
    float4 ss = make_float4(0,0,0,0);
    for (int r = r0 + rl; r < rend; r += rstep){
        float4 v = *(const float4*)(X + (size_t)r*C + c4*4);
        s.x += v.x; s.y += v.y; s.z += v.z; s.w += v.w;
        ss.x += v.x*v.x; ss.y += v.y*v.y; ss.z += v.z*v.z; ss.w += v.w*v.w;
    }
    atomicAdd(&sb[c4*4+0], s.x);  atomicAdd(&sb[c4*4+1], s.y);
    atomicAdd(&sb[c4*4+2], s.z);  atomicAdd(&sb[c4*4+3], s.w);
    atomicAdd(&sb[C+c4*4+0], ss.x); atomicAdd(&sb[C+c4*4+1], ss.y);
    atomicAdd(&sb[C+c4*4+2], ss.z); atomicAdd(&sb[C+c4*4+3], ss.w);
    __syncthreads();
    for (int i = t; i < 2*C; i += 256)
        atomicAdd(&out[i], (double)sb[i]);
}

__global__ void k_fin(const double* st, const float* __restrict__ g,
                      const float* __restrict__ b, float* sc, float* sh, double cnt){
    int c = threadIdx.x, C = blockDim.x;
    double m = st[c] / cnt;
    double v = st[C + c] / cnt - m*m;
    double s = (double)g[c] / sqrt(v + 1e-3);
    sc[c] = (float)s;
    sh[c] = (float)((double)b[c] - m*s);
}

__global__ void k_segsum(const float* __restrict__ pts, const float* __restrict__ pcyl,
                         const int* __restrict__ binv, const int* __restrict__ cinv, int n){
    int p = blockIdx.x*blockDim.x + threadIdx.x;
    if (p >= n) return;
    int bi = binv[p], ci = cinv[p];
    atomicAdd(&g_bev_acc[bi*4+0], pts[p*5+1]);
    atomicAdd(&g_bev_acc[bi*4+1], pts[p*5+2]);
    atomicAdd(&g_bev_acc[bi*4+2], pts[p*5+3]);
    atomicAdd(&g_bev_acc[bi*4+3], 1.f);
    atomicAdd(&g_cyl_acc[ci*4+0], pcyl[p*3+0]);
    atomicAdd(&g_cyl_acc[ci*4+1], pcyl[p*3+1]);
    atomicAdd(&g_cyl_acc[ci*4+2], pcyl[p*3+2]);
    atomicAdd(&g_cyl_acc[ci*4+3], 1.f);
}

__global__ void k_mvf_gemm1(const float* __restrict__ pts, const float* __restrict__ pcyl,
                            const float* __restrict__ cylidx, const float* __restrict__ bevidx,
                            const int* __restrict__ binv, const int* __restrict__ cinv,
                            const float* __restrict__ w1, int n){
    __shared__ float w1s[1024];
    int t = threadIdx.x;
    for (int i = t; i < 1024; i += 256) w1s[i] = w1[i];
    __syncthreads();
    int p = blockIdx.x*256 + t;
    if (p >= n) return;

    float x = pts[p*5+1], y = pts[p*5+2], z = pts[p*5+3], inten = pts[p*5+4];
    float ph = pcyl[p*3+0], zc = pcyl[p*3+1], rh = pcyl[p*3+2];
    float bc0 = floorf(bevidx[p*2+0]), bc1 = floorf(bevidx[p*2+1]);
    float cc0 = floorf(cylidx[p*2+0]), cc1 = floorf(cylidx[p*2+1]);

    int bi = binv[p], ci = cinv[p];
    float4 ba = *(const float4*)&g_bev_acc[bi*4];
    float4 ca = *(const float4*)&g_cyl_acc[ci*4];

    const float CVS0 = (float)((3.14159265 + 3.14159265) / 512.0);
    float f[16];
    f[0]=x; f[1]=y; f[2]=z; f[3]=ph; f[4]=zc; f[5]=rh;
    f[6]=x - ((bc0+0.5f)*0.32f);
    f[7]=y - ((bc1+0.5f)*0.32f - 40.0f);
    f[8]=ph - ((cc0+0.5f)*CVS0 - 3.14159265f);
    f[9]=zc - ((cc1+0.5f)*0.125f - 2.0f);
    f[10]=x - ba.x/ba.w; f[11]=y - ba.y/ba.w;
    f[12]=ph - ca.x/ca.w; f[13]=zc - ca.y/ca.w;
    f[14]=sqrtf(x*x + y*y + z*z);
    f[15]=inten;

    float* outp = g_h1 + (size_t)p*64;
    #pragma unroll
    for (int og = 0; og < 16; og++){
        const float* wr = w1s + og*64;
        float o0=0.f,o1=0.f,o2=0.f,o3=0.f;
        #pragma unroll
        for (int k = 0; k < 16; k++){
            float fk = f[k];
            o0 += fk*wr[k];    o1 += fk*wr[16+k];
            o2 += fk*wr[32+k]; o3 += fk*wr[48+k];
        }
        *(float4*)(outp + og*4) = make_float4(o0,o1,o2,o3);
    }
}

// h2[Nx128] = bnrelu(h1)[Nx64] @ w2^T  (R4-proven: 64-pt blocks, 8x4 per thread)
__global__ void __launch_bounds__(256) k_gemm2(const float* __restrict__ w2, int n){
    extern __shared__ float sm[];
    float* As = sm;            // [64][65]
    float* Bs = sm + 64*65;    // [64][132]
    int t = threadIdx.x;
    int p0 = blockIdx.x * 64;

    for (int idx = t; idx < 8192; idx += 256){
        int o = idx >> 6, k = idx & 63;
        Bs[k*132 + o] = w2[idx];
    }
    for (int idx = t; idx < 4096; idx += 256){
        int pl = idx >> 6, k = idx & 63;
        int p = p0 + pl;
        float v = 0.f;
        if (p < n){
            v = g_h1[(size_t)p*64 + k];
            v = fmaxf(g_sc1[k]*v + g_sh1[k], 0.f);
        }
        As[k*65 + pl] = v;
    }
    __syncthreads();

    int o0 = (t & 31) * 4;
    int pq = (t >> 5) * 8;
    float acc[8][4];
    #pragma unroll
    for (int i=0;i<8;i++){ acc[i][0]=0;acc[i][1]=0;acc[i][2]=0;acc[i][3]=0; }

    for (int k = 0; k < 64; k++){
        float4 bv = *(const float4*)(Bs + k*132 + o0);
        #pragma unroll
        for (int i = 0; i < 8; i++){
            float a = As[k*65 + pq + i];
            acc[i][0] += a*bv.x; acc[i][1] += a*bv.y;
            acc[i][2] += a*bv.z; acc[i][3] += a*bv.w;
        }
    }
    #pragma unroll
    for (int i = 0; i < 8; i++){
        int p = p0 + pq + i;
        if (p < n)
            *(float4*)(g_h2 + (size_t)p*128 + o0) =
                make_float4(acc[i][0],acc[i][1],acc[i][2],acc[i][3]);
    }
}

__global__ void k_scatmax(const float* __restrict__ pts, const float* __restrict__ cylidx, int n){
    int p = blockIdx.x*256 + threadIdx.x;
    if (p >= n) return;
    int b  = (int)pts[p*5];
    int cx = (int)floorf(cylidx[p*2+0]);
    int cy = (int)floorf(cylidx[p*2+1]);
    size_t base0 = ((size_t)(b*64)*GCX + cx)*GCY + cy;
    const float4* hp = (const float4*)(g_h2 + (size_t)p*128);
    #pragma unroll
    for (int q = 0; q < 16; q++){
        float4 h = hp[q];
        float hv[4] = {h.x,h.y,h.z,h.w};
        #pragma unroll
        for (int j = 0; j < 4; j++){
            int c = q*4 + j;
            float v = fmaxf(g_sc2[c]*hv[j] + g_sh2[c], 0.f);
            atomicMax((unsigned int*)&g_img_in[base0 + (size_t)c*(GCX*GCY)], __float_as_uint(v));
        }
    }
}

// conv 3x3 SAME, 64->64, [b][c][512][48] -> channel-last [b][512][48][64]  (R4 proven)
__global__ void __launch_bounds__(384,2) k_conv(const float* __restrict__ wcp){
    extern __shared__ float sm[];
    float* in_s = sm;          // [16][6][50]
    float* w_s  = sm + 4800;   // [16*9][64]
    int t = threadIdx.x;
    int ocg = t & 7;
    int yg  = (t >> 3) % 12;
    int xl  = t / 96;
    int b = blockIdx.y;
    int x0 = blockIdx.x * 4;
    int oc0 = ocg*8, y0 = yg*4;

    float acc[8][4];
    #pragma unroll
    for (int o=0;o<8;o++){ acc[o][0]=0;acc[o][1]=0;acc[o][2]=0;acc[o][3]=0; }

    for (int icc = 0; icc < 4; icc++){
        __syncthreads();
        for (int idx = t; idx < 4800; idx += 384){
            int ic = idx / 300, r = idx % 300;
            int sx = r / 50, yy = r % 50;
            int gx = x0 - 1 + sx, gy = yy - 1;
            float v = 0.f;
            if (gx >= 0 && gx < GCX && gy >= 0 && gy < GCY)
                v = g_img_in[((size_t)(b*64 + icc*16 + ic)*GCX + gx)*GCY + gy];
            in_s[idx] = v;
        }
        for (int idx = t; idx < 9216; idx += 384){
            int oc = idx / 144, r = idx % 144;
            int ic = r / 9, tap = r % 9;
            w_s[(ic*9 + tap)*64 + oc] = wcp[((size_t)oc*64 + icc*16 + ic)*9 + tap];
        }
        __syncthreads();

        #pragma unroll 2
        for (int ic = 0; ic < 16; ic++){
            #pragma unroll
            for (int dx = 0; dx < 3; dx++){
                float iv[6];
                int base = (ic*6 + xl + dx)*50 + y0;
                #pragma unroll
                for (int j = 0; j < 6; j++) iv[j] = in_s[base + j];
                #pragma unroll
                for (int dy = 0; dy < 3; dy++){
                    const float* wr = w_s + (ic*9 + dx*3 + dy)*64 + oc0;
                    float4 wA = *(const float4*)wr;
                    float4 wB = *(const float4*)(wr + 4);
                    #pragma unroll
                    for (int i = 0; i < 4; i++){
                        float v = iv[dy + i];
                        acc[0][i] += wA.x*v; acc[1][i] += wA.y*v;
                        acc[2][i] += wA.z*v; acc[3][i] += wA.w*v;
                        acc[4][i] += wB.x*v; acc[5][i] += wB.y*v;
                        acc[6][i] += wB.z*v; acc[7][i] += wB.w*v;
                    }
                }
            }
        }
    }
    int X = x0 + xl;
    #pragma unroll
    for (int i = 0; i < 4; i++){
        size_t addr = ((size_t)(b*GCX + X)*GCY + (y0 + i))*64 + oc0;
        *(float4*)(g_gimg + addr)     = make_float4(acc[0][i],acc[1][i],acc[2][i],acc[3][i]);
        *(float4*)(g_gimg + addr + 4) = make_float4(acc[4][i],acc[5][i],acc[6][i],acc[7][i]);
    }
}

// h3[Nx64] = [bnrelu(h2[:,64:]) , bilerp(bnrelu_conv(gimg))] @ w3^T  (R4-proven)
__global__ void __launch_bounds__(256) k_gemm3(const float* __restrict__ pts,
                                               const float* __restrict__ cylidx,
                                               const float* __restrict__ w3, int n){
    extern __shared__ float sm[];
    float* As = sm;            // [128][65]
    float* Bs = sm + 128*65;   // [128][68]
    int t = threadIdx.x;
    int p0 = blockIdx.x * 64;

    for (int idx = t; idx < 8192; idx += 256){
        int o = idx >> 7, k = idx & 127;
        Bs[k*68 + o] = w3[idx];
    }
    for (int idx = t; idx < 4096; idx += 256){
        int pl = idx >> 6, j = idx & 63;
        int p = p0 + pl;
        float v = 0.f;
        if (p < n){
            v = g_h2[(size_t)p*128 + 64 + j];
            v = fmaxf(g_sc2[64+j]*v + g_sh2[64+j], 0.f);
        }
        As[j*65 + pl] = v;
    }
    {
        int pl = t >> 2, seg = t & 3;
        int p = p0 + pl;
        int c0 = seg*16;
        if (p < n){
            float yq = cylidx[p*2+0], xq = cylidx[p*2+1];
            int y0i = (int)floorf(yq), y1i = y0i + 1;
            y0i = min(max(y0i,0), GCX-1); y1i = min(max(y1i,0), GCX-1);
            int x0i = (int)floorf(xq), x1i = x0i + 1;
            x0i = min(max(x0i,0), GCY-1); x1i = min(max(x1i,0), GCY-1);
            float x0f=(float)x0i, x1f=(float)x1i, y0f=(float)y0i, y1f=(float)y1i;
            float wa  = (x1f-xq)*(y1f-yq);
            float wb2 = (x1f-xq)*(yq-y0f);
            float wc2 = (xq-x0f)*(y1f-yq);
            float wd  = (xq-x0f)*(yq-y0f);
            int b = (int)pts[p*5];
            size_t ba_ = ((size_t)(b*GCX + y0i)*GCY + x0i)*64;
            size_t bb_ = ((size_t)(b*GCX + y1i)*GCY + x0i)*64;
            size_t bc_ = ((size_t)(b*GCX + y0i)*GCY + x1i)*64;
            size_t bd_ = ((size_t)(b*GCX + y1i)*GCY + x1i)*64;
            #pragma unroll
            for (int q = 0; q < 4; q++){
                int c = c0 + q*4;
                float4 A4 = *(const float4*)(g_gimg + ba_ + c);
                float4 B4 = *(const float4*)(g_gimg + bb_ + c);
                float4 C4 = *(const float4*)(g_gimg + bc_ + c);
                float4 D4 = *(const float4*)(g_gimg + bd_ + c);
                float Af[4]={A4.x,A4.y,A4.z,A4.w};
                float Bf[4]={B4.x,B4.y,B4.z,B4.w};
                float Cf[4]={C4.x,C4.y,C4.z,C4.w};
                float Df[4]={D4.x,D4.y,D4.z,D4.w};
                #pragma unroll
                for (int j = 0; j < 4; j++){
                    int cc2 = c + j;
                    float s = g_scC[cc2], h = g_shC[cc2];
                    float va = fmaxf(s*Af[j] + h, 0.f);
                    float vb = fmaxf(s*Bf[j] + h, 0.f);
                    float vc = fmaxf(s*Cf[j] + h, 0.f);
                    float vd = fmaxf(s*Df[j] + h, 0.f);
                    As[(64 + cc2)*65 + pl] = wa*va + wb2*vb + wc2*vc + wd*vd;
                }
            }
        } else {
            #pragma unroll
            for (int q = 0; q < 16; q++) As[(64 + c0 + q)*65 + pl] = 0.f;
        }
    }
    __syncthreads();

    int o0 = (t & 15) * 4;
    int pq = (t >> 4) * 4;
    float acc[4][4];
    #pragma unroll
    for (int i=0;i<4;i++){ acc[i][0]=0;acc[i][1]=0;acc[i][2]=0;acc[i][3]=0; }

    for (int k = 0; k < 128; k++){
        float4 bv = *(const float4*)(Bs + k*68 + o0);
        #pragma unroll
        for (int i = 0; i < 4; i++){
            float a = As[k*65 + pq + i];
            acc[i][0] += a*bv.x; acc[i][1] += a*bv.y;
            acc[i][2] += a*bv.z; acc[i][3] += a*bv.w;
        }
    }
    #pragma unroll
    for (int i = 0; i < 4; i++){
        int p = p0 + pq + i;
        if (p < n)
            *(float4*)(g_h3 + (size_t)p*64 + o0) =
                make_float4(acc[i][0],acc[i][1],acc[i][2],acc[i][3]);
    }
}

__global__ void k_out(const int* __restrict__ binv, float* __restrict__ out, int n){
    int p = blockIdx.x*256 + threadIdx.x;
    if (p >= n) return;
    int bi = binv[p];
    float* op = out + (size_t)p*64;
    float* mp = out + (size_t)n*64 + (size_t)bi*64;
    const float4* hp = (const float4*)(g_h3 + (size_t)p*64);
    #pragma unroll
    for (int q = 0; q < 16; q++){
        float4 h = hp[q];
        float hv[4] = {h.x,h.y,h.z,h.w};
        float rv[4];
        #pragma unroll
        for (int j = 0; j < 4; j++){
            int c = q*4 + j;
            rv[j] = fmaxf(g_sc3[c]*hv[j] + g_sh3[c], 0.f);
            atomicMax((unsigned int*)&mp[c], __float_as_uint(rv[j]));
        }
        *(float4*)(op + q*4) = make_float4(rv[0],rv[1],rv[2],rv[3]);
    }
}

__global__ void k_voxel(const int* __restrict__ coords, float* __restrict__ out, int n, int nb){
    int i = blockIdx.x*blockDim.x + threadIdx.x;
    if (i >= nb) return;
    int c = coords[i];
    int vb = c / BEV_SXY;
    int rem = c % BEV_SXY;
    float* o = out + (size_t)n*64 + (size_t)nb*64 + (size_t)i*4;
    o[0] = (float)vb; o[1] = 0.f;
    o[2] = (float)(rem % BEV_SY); o[3] = (float)(rem / BEV_SY);
}

static inline int cdiv(int a, int b){ return (a + b - 1) / b; }

extern "C" void kernel_launch(void* const* d_in, const int* in_sizes, int n_in,
                              void* d_out, int out_size){
    const float* pts    = (const float*)d_in[0];
    const float* pcyl   = (const float*)d_in[1];
    const float* cylidx = (const float*)d_in[2];
    const float* bevidx = (const float*)d_in[3];
    const float* w1 = (const float*)d_in[4];
    const float* g1 = (const float*)d_in[5];
    const float* b1 = (const float*)d_in[6];
    const float* w2 = (const float*)d_in[7];
    const float* g2 = (const float*)d_in[8];
    const float* b2 = (const float*)d_in[9];
    const float* wcp = (const float*)d_in[10];
    const float* gc = (const float*)d_in[11];
    const float* bc = (const float*)d_in[12];
    const float* w3 = (const float*)d_in[13];
    const float* g3 = (const float*)d_in[14];
    const float* b3 = (const float*)d_in[15];
    const int* binv    = (const int*)d_in[16];
    const int* bcoords = (const int*)d_in[17];
    const int* cinv    = (const int*)d_in[18];
    (void)n_in; (void)out_size;

    int N  = in_sizes[16];
    int Nb = in_sizes[17];
    float* out = (float*)d_out;

    float *p_bev,*p_gimg,*p_h1,*p_h2,*p_h3;
    float *p_sc1,*p_sh1,*p_sc2,*p_sh2,*p_sc3,*p_sh3,*p_scC,*p_shC;
    double* p_st;
    cudaGetSymbolAddress((void**)&p_bev,  g_bev_acc);
    cudaGetSymbolAddress((void**)&p_gimg, g_gimg);
    cudaGetSymbolAddress((void**)&p_h1,   g_h1);
    cudaGetSymbolAddress((void**)&p_h2,   g_h2);
    cudaGetSymbolAddress((void**)&p_h3,   g_h3);
    cudaGetSymbolAddress((void**)&p_st,   g_stats);
    cudaGetSymbolAddress((void**)&p_sc1,  g_sc1);
    cudaGetSymbolAddress((void**)&p_sh1,  g_sh1);
    cudaGetSymbolAddress((void**)&p_sc2,  g_sc2);
    cudaGetSymbolAddress((void**)&p_sh2,  g_sh2);
    cudaGetSymbolAddress((void**)&p_sc3,  g_sc3);
    cudaGetSymbolAddress((void**)&p_sh3,  g_sh3);
    cudaGetSymbolAddress((void**)&p_scC,  g_scC);
    cudaGetSymbolAddress((void**)&p_shC,  g_shC);

    k_zeroall<<<27024,256>>>(p_bev, Nb*4, out + (size_t)N*64, Nb*64);

    k_segsum<<<cdiv(N,256),256>>>(pts, pcyl, binv, cinv, N);
    k_mvf_gemm1<<<cdiv(N,256),256>>>(pts, pcyl, cylidx, bevidx, binv, cinv, w1, N);
    k_stats<<<512,256>>>(p_h1, N, 64, p_st + 0);
    k_fin<<<1,64>>>(p_st + 0, g1, b1, p_sc1, p_sh1, (double)N);

    cudaFuncSetAttribute(k_gemm2, cudaFuncAttributeMaxDynamicSharedMemorySize, 50432);
    k_gemm2<<<cdiv(N,64),256,50432>>>(w2, N);
    k_stats<<<512,256>>>(p_h2, N, 128, p_st + 128);
    k_fin<<<1,128>>>(p_st + 128, g2, b2, p_sc2, p_sh2, (double)N);

    k_scatmax<<<cdiv(N,256),256>>>(pts, cylidx, N);

    cudaFuncSetAttribute(k_conv, cudaFuncAttributeMaxDynamicSharedMemorySize, 56064);
    k_conv<<<dim3(128,4),384,56064>>>(wcp);
    k_stats<<<512,256>>>(p_gimg, 4*GCX*GCY, 64, p_st + 512);
    k_fin<<<1,64>>>(p_st + 512, gc, bc, p_scC, p_shC, (double)(4*GCX*GCY));

    cudaFuncSetAttribute(k_gemm3, cudaFuncAttributeMaxDynamicSharedMemorySize, 68096);
    k_gemm3<<<cdiv(N,64),256,68096>>>(pts, cylidx, w3, N);
    k_stats<<<512,256>>>(p_h3, N, 64, p_st + 384);
    k_fin<<<1,64>>>(p_st + 384, g3, b3, p_sc3, p_sh3, (double)N);

    k_out<<<cdiv(N,256),256>>>(binv, out, N);
    k_voxel<<<cdiv(Nb,256),256>>>(bcoords, out, N, Nb);
}